// round 1
// baseline (speedup 1.0000x reference)
#include <cuda_runtime.h>
#include <math.h>

#define B_   8
#define C_   512
#define HW_  1024
#define M_   (B_*HW_)     // 8192 tokens
#define HID_ 2048

// ---------------- scratch (device globals; no allocation) ----------------
__device__ float g_Xs[M_*C_];
__device__ float g_Xf[M_*C_];
__device__ float g_Qb[M_*C_];
__device__ float g_Kb[M_*C_];
__device__ float g_Vb[M_*C_];
__device__ float g_Ab[M_*C_];
__device__ float g_Eb[M_*C_];
__device__ float g_Sb[M_*C_];
__device__ float g_Hb[M_*HID_];
__device__ float g_Fb[M_*C_];
__device__ float g_Ob[M_*C_];

// ---------------- batched transpose: out[b][c][r] = in[b][r][c] ----------------
__global__ void __launch_bounds__(256) btranspose(const float* __restrict__ in,
                                                  float* __restrict__ out,
                                                  int R, int Ccols) {
  __shared__ float t[32][33];
  int b = blockIdx.z;
  const float* pin = in + (size_t)b * R * Ccols;
  float* pout = out + (size_t)b * R * Ccols;
  int c0 = blockIdx.x * 32, r0 = blockIdx.y * 32;
  int x = threadIdx.x, y = threadIdx.y;  // (32, 8)
#pragma unroll
  for (int j = 0; j < 32; j += 8)
    t[y + j][x] = pin[(size_t)(r0 + y + j) * Ccols + c0 + x];
  __syncthreads();
#pragma unroll
  for (int j = 0; j < 32; j += 8)
    pout[(size_t)(c0 + y + j) * R + r0 + x] = t[x][y + j];
}

// ---------------- GEMM: C[M,N] = A[M,K] @ W[N,K]^T + bias (opt GELU) ----------------
__device__ __forceinline__ float gelu_exact(float v) {
  return 0.5f * v * (1.0f + erff(v * 0.70710678118654752f));
}

template <int DO_GELU>
__global__ void __launch_bounds__(256) gemm_nt(const float* __restrict__ A,
                                               const float* __restrict__ W,
                                               const float* __restrict__ bias,
                                               float* __restrict__ Cout,
                                               int M, int N, int K) {
  __shared__ float As[16][128];
  __shared__ float Bs[16][128];
  const float* Ab = A + (size_t)blockIdx.y * 128 * K;
  const float* Wb = W + (size_t)blockIdx.x * 128 * K;
  int tid = threadIdx.x;
  int tx = tid & 15, ty = tid >> 4;
  float acc[8][8];
#pragma unroll
  for (int i = 0; i < 8; i++)
#pragma unroll
    for (int j = 0; j < 8; j++) acc[i][j] = 0.f;

  for (int kt = 0; kt < K; kt += 16) {
#pragma unroll
    for (int s = 0; s < 2; s++) {
      int idx = tid + s * 256;
      int row = idx >> 2;
      int c4 = (idx & 3) * 4;
      float4 va = *(const float4*)(Ab + (size_t)row * K + kt + c4);
      As[c4 + 0][row] = va.x; As[c4 + 1][row] = va.y;
      As[c4 + 2][row] = va.z; As[c4 + 3][row] = va.w;
      float4 vb = *(const float4*)(Wb + (size_t)row * K + kt + c4);
      Bs[c4 + 0][row] = vb.x; Bs[c4 + 1][row] = vb.y;
      Bs[c4 + 2][row] = vb.z; Bs[c4 + 3][row] = vb.w;
    }
    __syncthreads();
#pragma unroll
    for (int k = 0; k < 16; k++) {
      float4 a0 = *(const float4*)&As[k][ty * 8];
      float4 a1 = *(const float4*)&As[k][ty * 8 + 4];
      float4 b0 = *(const float4*)&Bs[k][tx * 8];
      float4 b1 = *(const float4*)&Bs[k][tx * 8 + 4];
      float av[8] = {a0.x, a0.y, a0.z, a0.w, a1.x, a1.y, a1.z, a1.w};
      float bv[8] = {b0.x, b0.y, b0.z, b0.w, b1.x, b1.y, b1.z, b1.w};
#pragma unroll
      for (int i = 0; i < 8; i++)
#pragma unroll
        for (int j = 0; j < 8; j++) acc[i][j] += av[i] * bv[j];
    }
    __syncthreads();
  }

  int gn = blockIdx.x * 128 + tx * 8;
  float bv[8];
#pragma unroll
  for (int j = 0; j < 8; j++) bv[j] = bias ? bias[gn + j] : 0.f;
#pragma unroll
  for (int i = 0; i < 8; i++) {
    int gm = blockIdx.y * 128 + ty * 8 + i;
    float* crow = Cout + (size_t)gm * N + gn;
    float o[8];
#pragma unroll
    for (int j = 0; j < 8; j++) {
      float v = acc[i][j] + bv[j];
      o[j] = DO_GELU ? gelu_exact(v) : v;
    }
    *(float4*)crow = make_float4(o[0], o[1], o[2], o[3]);
    *(float4*)(crow + 4) = make_float4(o[4], o[5], o[6], o[7]);
  }
}

// ---------------- flash attention: seq=1024, dh=64, per (b,h) ----------------
// grid (16 qtiles, 8 heads, 8 batch), 256 threads (8 warps x 8 qrows each)
#define ATT_SMEM ((64*64 + 64*66 + 64*64 + 64*68) * 4)  // Qs, KsT, Vs, Ps = 67072 B

__global__ void __launch_bounds__(256) attn_kernel(const float* __restrict__ Q,
                                                   const float* __restrict__ K,
                                                   const float* __restrict__ V,
                                                   float* __restrict__ O) {
  extern __shared__ float sm[];
  float (*Qs)[64]  = (float(*)[64])sm;
  float (*KsT)[66] = (float(*)[66])(sm + 64 * 64);
  float (*Vs)[64]  = (float(*)[64])(sm + 64 * 64 + 64 * 66);
  float (*Ps)[68]  = (float(*)[68])(sm + 64 * 64 + 64 * 66 + 64 * 64);

  int qt = blockIdx.x, h = blockIdx.y, b = blockIdx.z;
  int tid = threadIdx.x, warp = tid >> 5, lane = tid & 31;

  size_t base_q = ((size_t)(b * HW_ + qt * 64)) * C_ + h * 64;
#pragma unroll
  for (int s = 0; s < 4; s++) {
    int idx = tid + s * 256;
    int row = idx >> 4;
    int c4 = (idx & 15) * 4;
    *(float4*)&Qs[row][c4] = *(const float4*)(Q + base_q + (size_t)row * C_ + c4);
  }

  int r0 = warp * 8;
  float m_r[8], l_r[8], acc0[8], acc1[8];
#pragma unroll
  for (int r = 0; r < 8; r++) { m_r[r] = -1e30f; l_r[r] = 0.f; acc0[r] = 0.f; acc1[r] = 0.f; }

  for (int kt = 0; kt < 16; kt++) {
    __syncthreads();  // protects Qs (first iter) and prev-iter smem reuse
    size_t base_k = ((size_t)(b * HW_ + kt * 64)) * C_ + h * 64;
#pragma unroll
    for (int s = 0; s < 4; s++) {
      int idx = tid + s * 256;
      int row = idx >> 4;
      int c4 = (idx & 15) * 4;
      float4 kv = *(const float4*)(K + base_k + (size_t)row * C_ + c4);
      KsT[c4 + 0][row] = kv.x; KsT[c4 + 1][row] = kv.y;
      KsT[c4 + 2][row] = kv.z; KsT[c4 + 3][row] = kv.w;
      *(float4*)&Vs[row][c4] = *(const float4*)(V + base_k + (size_t)row * C_ + c4);
    }
    __syncthreads();

    // S = Q @ K^T : lane owns kv columns {2*lane, 2*lane+1}
    float s0[8], s1[8];
#pragma unroll
    for (int r = 0; r < 8; r++) { s0[r] = 0.f; s1[r] = 0.f; }
#pragma unroll
    for (int d0 = 0; d0 < 64; d0 += 4) {
      float2 k0 = *(const float2*)&KsT[d0 + 0][2 * lane];
      float2 k1 = *(const float2*)&KsT[d0 + 1][2 * lane];
      float2 k2 = *(const float2*)&KsT[d0 + 2][2 * lane];
      float2 k3 = *(const float2*)&KsT[d0 + 3][2 * lane];
#pragma unroll
      for (int r = 0; r < 8; r++) {
        float4 q = *(const float4*)&Qs[r0 + r][d0];
        s0[r] += q.x * k0.x + q.y * k1.x + q.z * k2.x + q.w * k3.x;
        s1[r] += q.x * k0.y + q.y * k1.y + q.z * k2.y + q.w * k3.y;
      }
    }

    // online softmax per q-row
#pragma unroll
    for (int r = 0; r < 8; r++) {
      float a = s0[r] * 0.125f;  // dh^-0.5 = 64^-0.5
      float c = s1[r] * 0.125f;
      float mx = fmaxf(a, c);
#pragma unroll
      for (int off = 16; off > 0; off >>= 1)
        mx = fmaxf(mx, __shfl_xor_sync(0xffffffffu, mx, off));
      float mn = fmaxf(m_r[r], mx);
      float p0 = __expf(a - mn), p1 = __expf(c - mn);
      float ps = p0 + p1;
#pragma unroll
      for (int off = 16; off > 0; off >>= 1)
        ps += __shfl_xor_sync(0xffffffffu, ps, off);
      float corr = __expf(m_r[r] - mn);
      l_r[r] = l_r[r] * corr + ps;
      m_r[r] = mn;
      acc0[r] *= corr;
      acc1[r] *= corr;
      *(float2*)&Ps[r0 + r][2 * lane] = make_float2(p0, p1);
    }
    __syncwarp();

    // O += P @ V : lane owns d columns {2*lane, 2*lane+1}
#pragma unroll
    for (int c0 = 0; c0 < 64; c0 += 4) {
      float2 v0 = *(const float2*)&Vs[c0 + 0][2 * lane];
      float2 v1 = *(const float2*)&Vs[c0 + 1][2 * lane];
      float2 v2 = *(const float2*)&Vs[c0 + 2][2 * lane];
      float2 v3 = *(const float2*)&Vs[c0 + 3][2 * lane];
#pragma unroll
      for (int r = 0; r < 8; r++) {
        float4 p = *(const float4*)&Ps[r0 + r][c0];
        acc0[r] += p.x * v0.x + p.y * v1.x + p.z * v2.x + p.w * v3.x;
        acc1[r] += p.x * v0.y + p.y * v1.y + p.z * v2.y + p.w * v3.y;
      }
    }
  }

#pragma unroll
  for (int r = 0; r < 8; r++) {
    float inv = 1.0f / l_r[r];
    size_t o = ((size_t)(b * HW_ + qt * 64 + r0 + r)) * C_ + h * 64 + 2 * lane;
    *(float2*)&O[o] = make_float2(acc0[r] * inv, acc1[r] * inv);
  }
}

// ---------------- LayerNorm(X + Y) over C, one warp per token-row ----------------
__global__ void __launch_bounds__(256) ln_res(const float* __restrict__ X,
                                              const float* __restrict__ Y,
                                              const float* __restrict__ w,
                                              const float* __restrict__ bb,
                                              float* __restrict__ out) {
  int row = blockIdx.x * 8 + (threadIdx.x >> 5);
  int lane = threadIdx.x & 31;
  const float* px = X + (size_t)row * C_;
  const float* py = Y + (size_t)row * C_;
  float v[16];
  float s = 0.f;
#pragma unroll
  for (int i = 0; i < 16; i++) {
    v[i] = px[lane + 32 * i] + py[lane + 32 * i];
    s += v[i];
  }
#pragma unroll
  for (int off = 16; off > 0; off >>= 1) s += __shfl_xor_sync(0xffffffffu, s, off);
  float mean = s * (1.0f / C_);
  float s2 = 0.f;
#pragma unroll
  for (int i = 0; i < 16; i++) {
    float d = v[i] - mean;
    s2 += d * d;
  }
#pragma unroll
  for (int off = 16; off > 0; off >>= 1) s2 += __shfl_xor_sync(0xffffffffu, s2, off);
  float inv = rsqrtf(s2 * (1.0f / C_) + 1e-6f);
  float* po = out + (size_t)row * C_;
#pragma unroll
  for (int i = 0; i < 16; i++) {
    int c = lane + 32 * i;
    po[c] = (v[i] - mean) * inv * w[c] + bb[c];
  }
}

// ---------------- launch ----------------
extern "C" void kernel_launch(void* const* d_in, const int* in_sizes, int n_in,
                              void* d_out, int out_size) {
  (void)in_sizes; (void)n_in; (void)out_size;
  const float* spatial = (const float*)d_in[0];
  const float* freq    = (const float*)d_in[1];
  const float* Wq[2] = {(const float*)d_in[2],  (const float*)d_in[7]};
  const float* Wk[2] = {(const float*)d_in[3],  (const float*)d_in[8]};
  const float* Wv[2] = {(const float*)d_in[4],  (const float*)d_in[9]};
  const float* Wo[2] = {(const float*)d_in[5],  (const float*)d_in[10]};
  const float* bo[2] = {(const float*)d_in[6],  (const float*)d_in[11]};
  const float* n1w[2] = {(const float*)d_in[12], (const float*)d_in[16]};
  const float* n1b[2] = {(const float*)d_in[13], (const float*)d_in[17]};
  const float* n2w[2] = {(const float*)d_in[14], (const float*)d_in[18]};
  const float* n2b[2] = {(const float*)d_in[15], (const float*)d_in[19]};
  const float* W1[2] = {(const float*)d_in[20], (const float*)d_in[24]};
  const float* b1[2] = {(const float*)d_in[21], (const float*)d_in[25]};
  const float* W2[2] = {(const float*)d_in[22], (const float*)d_in[26]};
  const float* b2[2] = {(const float*)d_in[23], (const float*)d_in[27]};
  float* out = (float*)d_out;

  float *Xs, *Xf, *Qp, *Kp, *Vp, *Ap, *Ep, *Sp, *Hp, *Fp, *Op;
  cudaGetSymbolAddress((void**)&Xs, g_Xs);
  cudaGetSymbolAddress((void**)&Xf, g_Xf);
  cudaGetSymbolAddress((void**)&Qp, g_Qb);
  cudaGetSymbolAddress((void**)&Kp, g_Kb);
  cudaGetSymbolAddress((void**)&Vp, g_Vb);
  cudaGetSymbolAddress((void**)&Ap, g_Ab);
  cudaGetSymbolAddress((void**)&Ep, g_Eb);
  cudaGetSymbolAddress((void**)&Sp, g_Sb);
  cudaGetSymbolAddress((void**)&Hp, g_Hb);
  cudaGetSymbolAddress((void**)&Fp, g_Fb);
  cudaGetSymbolAddress((void**)&Op, g_Ob);

  cudaFuncSetAttribute(attn_kernel, cudaFuncAttributeMaxDynamicSharedMemorySize, ATT_SMEM);

  dim3 tp_threads(32, 8);
  // (B,C,HW) -> (B,HW,C): R=C, Ccols=HW
  btranspose<<<dim3(HW_ / 32, C_ / 32, B_), tp_threads>>>(spatial, Xs, C_, HW_);
  btranspose<<<dim3(HW_ / 32, C_ / 32, B_), tp_threads>>>(freq, Xf, C_, HW_);

  for (int br = 0; br < 2; br++) {
    const float* Xq  = br ? Xf : Xs;
    const float* Xkv = br ? Xs : Xf;

    gemm_nt<0><<<dim3(C_ / 128, M_ / 128), 256>>>(Xq,  Wq[br], nullptr, Qp, M_, C_, C_);
    gemm_nt<0><<<dim3(C_ / 128, M_ / 128), 256>>>(Xkv, Wk[br], nullptr, Kp, M_, C_, C_);
    gemm_nt<0><<<dim3(C_ / 128, M_ / 128), 256>>>(Xkv, Wv[br], nullptr, Vp, M_, C_, C_);

    attn_kernel<<<dim3(16, 8, 8), 256, ATT_SMEM>>>(Qp, Kp, Vp, Ap);

    gemm_nt<0><<<dim3(C_ / 128, M_ / 128), 256>>>(Ap, Wo[br], bo[br], Ep, M_, C_, C_);
    ln_res<<<M_ / 8, 256>>>(Xq, Ep, n1w[br], n1b[br], Sp);
    gemm_nt<1><<<dim3(HID_ / 128, M_ / 128), 256>>>(Sp, W1[br], b1[br], Hp, M_, HID_, C_);
    gemm_nt<0><<<dim3(C_ / 128, M_ / 128), 256>>>(Hp, W2[br], b2[br], Fp, M_, C_, HID_);
    ln_res<<<M_ / 8, 256>>>(Sp, Fp, n2w[br], n2b[br], Op);

    // (B,HW,C) -> (B,C,HW): R=HW, Ccols=C
    btranspose<<<dim3(C_ / 32, HW_ / 32, B_), tp_threads>>>(Op, out + (size_t)br * M_ * C_, HW_, C_);
  }
}

// round 4
// speedup vs baseline: 1.6880x; 1.6880x over previous
#include <cuda_runtime.h>
#include <cuda_bf16.h>
#include <math.h>
#include <cstdint>

#define B_   8
#define C_   512
#define HW_  1024
#define M_   (B_*HW_)     // 8192 tokens
#define HID_ 2048

// ---------------- scratch (device globals; no allocation) ----------------
__device__ float g_Xs[M_*C_];
__device__ float g_Xf[M_*C_];
__device__ float g_Qb[M_*C_];
__device__ float g_Kb[M_*C_];
__device__ float g_Vb[M_*C_];
__device__ float g_Ab[M_*C_];
__device__ float g_Eb[M_*C_];
__device__ float g_Sb[M_*C_];
__device__ float g_Hb[M_*HID_];
__device__ float g_Fb[M_*C_];
__device__ float g_Ob[M_*C_];
__device__ __nv_bfloat16 g_Ahi[M_*HID_];
__device__ __nv_bfloat16 g_Alo[M_*HID_];
__device__ __nv_bfloat16 g_Whi[HID_*C_];
__device__ __nv_bfloat16 g_Wlo[HID_*C_];

// ==================== portable tensor-core helpers (sm_80-level PTX) ====================
__device__ __forceinline__ uint32_t smem_u32(const void* p) {
  uint32_t a;
  asm("{ .reg .u64 t; cvta.to.shared.u64 t, %1; cvt.u32.u64 %0, t; }" : "=r"(a) : "l"(p));
  return a;
}
__device__ __forceinline__ void ldm_x4(uint32_t* r, uint32_t addr) {
  asm volatile("ldmatrix.sync.aligned.m8n8.x4.shared.b16 {%0,%1,%2,%3}, [%4];"
               : "=r"(r[0]), "=r"(r[1]), "=r"(r[2]), "=r"(r[3]) : "r"(addr));
}
__device__ __forceinline__ void mma16816(float* d, const uint32_t* a, const uint32_t* b) {
  asm volatile("mma.sync.aligned.m16n8k16.row.col.f32.bf16.bf16.f32 "
               "{%0,%1,%2,%3}, {%4,%5,%6,%7}, {%8,%9}, {%0,%1,%2,%3};"
               : "+f"(d[0]), "+f"(d[1]), "+f"(d[2]), "+f"(d[3])
               : "r"(a[0]), "r"(a[1]), "r"(a[2]), "r"(a[3]), "r"(b[0]), "r"(b[1]));
}
__device__ __forceinline__ void cp16(uint32_t saddr, const void* g) {
  asm volatile("cp.async.cg.shared.global [%0], [%1], 16;" :: "r"(saddr), "l"(g));
}
__device__ __forceinline__ void cp_commit() { asm volatile("cp.async.commit_group;" ::: "memory"); }
template <int N>
__device__ __forceinline__ void cp_wait() { asm volatile("cp.async.wait_group %0;" :: "n"(N) : "memory"); }

// ==================== mma.sync GEMM: C[M,N] = A@W^T (+bias,+GELU) ====================
// A,W given as bf16 hi/lo splits, [rows,K] row-major. 3-term product.
// CTA 128x128, BK=32, 256 threads = 8 warps (4 m x 2 n), warp tile 32x64.
#define BKC 32
#define TSTRIDE 40                   // bf16 elems per smem row (80B, conflict-free ldmatrix)
#define TILE_B (128*TSTRIDE*2)       // 10240 B per operand tile
#define BUF_B  (4*TILE_B)            // Ahi,Alo,Whi,Wlo
#define GT_SMEM (2*BUF_B)            // 81920 B (double buffered)

__device__ __forceinline__ float gelu_exact(float v) {
  return 0.5f * v * (1.0f + erff(v * 0.70710678118654752f));
}

template <int DO_GELU>
__global__ void __launch_bounds__(256)
gemm_mma(const __nv_bfloat16* __restrict__ Ahi, const __nv_bfloat16* __restrict__ Alo,
         const __nv_bfloat16* __restrict__ Whi, const __nv_bfloat16* __restrict__ Wlo,
         const float* __restrict__ bias, float* __restrict__ Cout, int N, int K) {
  extern __shared__ char smem[];
  uint32_t sbase = smem_u32(smem);
  int tid = threadIdx.x, lane = tid & 31, warp = tid >> 5;
  int warp_m = warp & 3, warp_n = warp >> 2;   // 4 x 2
  int bn = blockIdx.x, bm = blockIdx.y;

  const __nv_bfloat16* src[4];
  src[0] = Ahi + (size_t)bm * 128 * K;
  src[1] = Alo + (size_t)bm * 128 * K;
  src[2] = Whi + (size_t)bn * 128 * K;
  src[3] = Wlo + (size_t)bn * 128 * K;

  // load one 128 x 32 bf16 chunk of each operand into buffer `buf`
  auto load_chunk = [&](int buf, int kt) {
    uint32_t bb = sbase + buf * BUF_B;
#pragma unroll
    for (int t = 0; t < 4; t++) {
      const __nv_bfloat16* s = src[t];
      uint32_t tb = bb + t * TILE_B;
#pragma unroll
      for (int i = 0; i < 2; i++) {
        int idx = i * 256 + tid;
        int row = idx >> 2, seg = idx & 3;
        cp16(tb + row * (TSTRIDE * 2) + seg * 16, s + (size_t)row * K + kt + seg * 8);
      }
    }
  };

  float acc[2][8][4];
#pragma unroll
  for (int t = 0; t < 2; t++)
#pragma unroll
    for (int n = 0; n < 8; n++)
#pragma unroll
      for (int j = 0; j < 4; j++) acc[t][n][j] = 0.f;

  int nk = K / BKC;
  load_chunk(0, 0);
  cp_commit();

  for (int i = 0; i < nk; i++) {
    if (i + 1 < nk) {
      load_chunk((i + 1) & 1, (i + 1) * BKC);
      cp_commit();
      cp_wait<1>();
    } else {
      cp_wait<0>();
    }
    __syncthreads();

    uint32_t bb = sbase + (i & 1) * BUF_B;
    uint32_t abase_hi = bb, abase_lo = bb + TILE_B;
    uint32_t wbase_hi = bb + 2 * TILE_B, wbase_lo = bb + 3 * TILE_B;

#pragma unroll
    for (int ks = 0; ks < 2; ks++) {
      // A fragments: 2 m16 tiles, hi+lo
      uint32_t a_hi[2][4], a_lo[2][4];
#pragma unroll
      for (int t = 0; t < 2; t++) {
        int row = warp_m * 32 + t * 16 + (lane & 15);
        uint32_t off = row * (TSTRIDE * 2) + ks * 32 + (lane >> 4) * 16;
        ldm_x4(a_hi[t], abase_hi + off);
        ldm_x4(a_lo[t], abase_lo + off);
      }
      // B fragments: 8 n8 tiles (4 x4-ldmatrix pairs), hi+lo
      uint32_t b_hi[8][2], b_lo[8][2];
#pragma unroll
      for (int p = 0; p < 4; p++) {
        int g = lane >> 3;
        int row = warp_n * 64 + p * 16 + ((g >> 1) << 3) + (lane & 7);
        uint32_t off = row * (TSTRIDE * 2) + (g & 1) * 16 + ks * 32;
        uint32_t r4[4];
        ldm_x4(r4, wbase_hi + off);
        b_hi[p * 2][0] = r4[0]; b_hi[p * 2][1] = r4[1];
        b_hi[p * 2 + 1][0] = r4[2]; b_hi[p * 2 + 1][1] = r4[3];
        ldm_x4(r4, wbase_lo + off);
        b_lo[p * 2][0] = r4[0]; b_lo[p * 2][1] = r4[1];
        b_lo[p * 2 + 1][0] = r4[2]; b_lo[p * 2 + 1][1] = r4[3];
      }
#pragma unroll
      for (int t = 0; t < 2; t++)
#pragma unroll
        for (int n = 0; n < 8; n++) {
          mma16816(acc[t][n], a_hi[t], b_hi[n]);
          mma16816(acc[t][n], a_hi[t], b_lo[n]);
          mma16816(acc[t][n], a_lo[t], b_hi[n]);
        }
    }
    __syncthreads();
  }

  // epilogue
  int q = lane >> 2, rr = lane & 3;
#pragma unroll
  for (int t = 0; t < 2; t++) {
    int row0 = bm * 128 + warp_m * 32 + t * 16 + q;
#pragma unroll
    for (int n = 0; n < 8; n++) {
      int col = bn * 128 + warp_n * 64 + n * 8 + rr * 2;
      float bx = bias ? bias[col] : 0.f;
      float by = bias ? bias[col + 1] : 0.f;
      float2 o0 = make_float2(acc[t][n][0] + bx, acc[t][n][1] + by);
      float2 o1 = make_float2(acc[t][n][2] + bx, acc[t][n][3] + by);
      if (DO_GELU) {
        o0.x = gelu_exact(o0.x); o0.y = gelu_exact(o0.y);
        o1.x = gelu_exact(o1.x); o1.y = gelu_exact(o1.y);
      }
      *(float2*)(Cout + (size_t)row0 * N + col) = o0;
      *(float2*)(Cout + (size_t)(row0 + 8) * N + col) = o1;
    }
  }
}

// ---------------- fp32 -> bf16 hi/lo split ----------------
__global__ void __launch_bounds__(256) cvt_split(const float* __restrict__ x,
                                                 __nv_bfloat16* __restrict__ hi,
                                                 __nv_bfloat16* __restrict__ lo) {
  int i = (blockIdx.x * 256 + threadIdx.x) * 4;
  float4 v = *(const float4*)(x + i);
  __nv_bfloat16 h0 = __float2bfloat16(v.x), h1 = __float2bfloat16(v.y);
  __nv_bfloat16 h2 = __float2bfloat16(v.z), h3 = __float2bfloat16(v.w);
  __nv_bfloat16 l0 = __float2bfloat16(v.x - __bfloat162float(h0));
  __nv_bfloat16 l1 = __float2bfloat16(v.y - __bfloat162float(h1));
  __nv_bfloat16 l2 = __float2bfloat16(v.z - __bfloat162float(h2));
  __nv_bfloat16 l3 = __float2bfloat16(v.w - __bfloat162float(h3));
  __nv_bfloat162 hp0; hp0.x = h0; hp0.y = h1;
  __nv_bfloat162 hp1; hp1.x = h2; hp1.y = h3;
  __nv_bfloat162 lp0; lp0.x = l0; lp0.y = l1;
  __nv_bfloat162 lp1; lp1.x = l2; lp1.y = l3;
  *(__nv_bfloat162*)(hi + i) = hp0; *(__nv_bfloat162*)(hi + i + 2) = hp1;
  *(__nv_bfloat162*)(lo + i) = lp0; *(__nv_bfloat162*)(lo + i + 2) = lp1;
}

// ---------------- batched transpose ----------------
__global__ void __launch_bounds__(256) btranspose(const float* __restrict__ in,
                                                  float* __restrict__ out,
                                                  int R, int Ccols) {
  __shared__ float t[32][33];
  int b = blockIdx.z;
  const float* pin = in + (size_t)b * R * Ccols;
  float* pout = out + (size_t)b * R * Ccols;
  int c0 = blockIdx.x * 32, r0 = blockIdx.y * 32;
  int x = threadIdx.x, y = threadIdx.y;
#pragma unroll
  for (int j = 0; j < 32; j += 8)
    t[y + j][x] = pin[(size_t)(r0 + y + j) * Ccols + c0 + x];
  __syncthreads();
#pragma unroll
  for (int j = 0; j < 32; j += 8)
    pout[(size_t)(c0 + y + j) * R + r0 + x] = t[x][y + j];
}

// ---------------- flash attention (fp32), seq=1024, dh=64 ----------------
#define ATT_SMEM ((64*64 + 64*66 + 64*64 + 64*68) * 4)

__global__ void __launch_bounds__(256) attn_kernel(const float* __restrict__ Q,
                                                   const float* __restrict__ K,
                                                   const float* __restrict__ V,
                                                   float* __restrict__ O) {
  extern __shared__ float sm[];
  float (*Qs)[64]  = (float(*)[64])sm;
  float (*KsT)[66] = (float(*)[66])(sm + 64 * 64);
  float (*Vs)[64]  = (float(*)[64])(sm + 64 * 64 + 64 * 66);
  float (*Ps)[68]  = (float(*)[68])(sm + 64 * 64 + 64 * 66 + 64 * 64);

  int qt = blockIdx.x, h = blockIdx.y, b = blockIdx.z;
  int tid = threadIdx.x, warp = tid >> 5, lane = tid & 31;

  size_t base_q = ((size_t)(b * HW_ + qt * 64)) * C_ + h * 64;
#pragma unroll
  for (int s = 0; s < 4; s++) {
    int idx = tid + s * 256;
    int row = idx >> 4, c4 = (idx & 15) * 4;
    *(float4*)&Qs[row][c4] = *(const float4*)(Q + base_q + (size_t)row * C_ + c4);
  }

  int r0 = warp * 8;
  float m_r[8], l_r[8], acc0[8], acc1[8];
#pragma unroll
  for (int r = 0; r < 8; r++) { m_r[r] = -1e30f; l_r[r] = 0.f; acc0[r] = 0.f; acc1[r] = 0.f; }

  for (int kt = 0; kt < 16; kt++) {
    __syncthreads();
    size_t base_k = ((size_t)(b * HW_ + kt * 64)) * C_ + h * 64;
#pragma unroll
    for (int s = 0; s < 4; s++) {
      int idx = tid + s * 256;
      int row = idx >> 4, c4 = (idx & 15) * 4;
      float4 kv = *(const float4*)(K + base_k + (size_t)row * C_ + c4);
      KsT[c4 + 0][row] = kv.x; KsT[c4 + 1][row] = kv.y;
      KsT[c4 + 2][row] = kv.z; KsT[c4 + 3][row] = kv.w;
      *(float4*)&Vs[row][c4] = *(const float4*)(V + base_k + (size_t)row * C_ + c4);
    }
    __syncthreads();

    float s0[8], s1[8];
#pragma unroll
    for (int r = 0; r < 8; r++) { s0[r] = 0.f; s1[r] = 0.f; }
#pragma unroll
    for (int d0 = 0; d0 < 64; d0 += 4) {
      float2 k0 = *(const float2*)&KsT[d0 + 0][2 * lane];
      float2 k1 = *(const float2*)&KsT[d0 + 1][2 * lane];
      float2 k2 = *(const float2*)&KsT[d0 + 2][2 * lane];
      float2 k3 = *(const float2*)&KsT[d0 + 3][2 * lane];
#pragma unroll
      for (int r = 0; r < 8; r++) {
        float4 q = *(const float4*)&Qs[r0 + r][d0];
        s0[r] += q.x * k0.x + q.y * k1.x + q.z * k2.x + q.w * k3.x;
        s1[r] += q.x * k0.y + q.y * k1.y + q.z * k2.y + q.w * k3.y;
      }
    }

#pragma unroll
    for (int r = 0; r < 8; r++) {
      float a = s0[r] * 0.125f, c = s1[r] * 0.125f;
      float mx = fmaxf(a, c);
#pragma unroll
      for (int off = 16; off > 0; off >>= 1)
        mx = fmaxf(mx, __shfl_xor_sync(0xffffffffu, mx, off));
      float mn = fmaxf(m_r[r], mx);
      float p0 = __expf(a - mn), p1 = __expf(c - mn);
      float ps = p0 + p1;
#pragma unroll
      for (int off = 16; off > 0; off >>= 1)
        ps += __shfl_xor_sync(0xffffffffu, ps, off);
      float corr = __expf(m_r[r] - mn);
      l_r[r] = l_r[r] * corr + ps;
      m_r[r] = mn;
      acc0[r] *= corr; acc1[r] *= corr;
      *(float2*)&Ps[r0 + r][2 * lane] = make_float2(p0, p1);
    }
    __syncwarp();

#pragma unroll
    for (int c0 = 0; c0 < 64; c0 += 4) {
      float2 v0 = *(const float2*)&Vs[c0 + 0][2 * lane];
      float2 v1 = *(const float2*)&Vs[c0 + 1][2 * lane];
      float2 v2 = *(const float2*)&Vs[c0 + 2][2 * lane];
      float2 v3 = *(const float2*)&Vs[c0 + 3][2 * lane];
#pragma unroll
      for (int r = 0; r < 8; r++) {
        float4 p = *(const float4*)&Ps[r0 + r][c0];
        acc0[r] += p.x * v0.x + p.y * v1.x + p.z * v2.x + p.w * v3.x;
        acc1[r] += p.x * v0.y + p.y * v1.y + p.z * v2.y + p.w * v3.y;
      }
    }
  }

#pragma unroll
  for (int r = 0; r < 8; r++) {
    float inv = 1.0f / l_r[r];
    size_t o = ((size_t)(b * HW_ + qt * 64 + r0 + r)) * C_ + h * 64 + 2 * lane;
    *(float2*)&O[o] = make_float2(acc0[r] * inv, acc1[r] * inv);
  }
}

// ---------------- LayerNorm(X + Y) over C ----------------
__global__ void __launch_bounds__(256) ln_res(const float* __restrict__ X,
                                              const float* __restrict__ Y,
                                              const float* __restrict__ w,
                                              const float* __restrict__ bb,
                                              float* __restrict__ out) {
  int row = blockIdx.x * 8 + (threadIdx.x >> 5);
  int lane = threadIdx.x & 31;
  const float* px = X + (size_t)row * C_;
  const float* py = Y + (size_t)row * C_;
  float v[16];
  float s = 0.f;
#pragma unroll
  for (int i = 0; i < 16; i++) {
    v[i] = px[lane + 32 * i] + py[lane + 32 * i];
    s += v[i];
  }
#pragma unroll
  for (int off = 16; off > 0; off >>= 1) s += __shfl_xor_sync(0xffffffffu, s, off);
  float mean = s * (1.0f / C_);
  float s2 = 0.f;
#pragma unroll
  for (int i = 0; i < 16; i++) { float d = v[i] - mean; s2 += d * d; }
#pragma unroll
  for (int off = 16; off > 0; off >>= 1) s2 += __shfl_xor_sync(0xffffffffu, s2, off);
  float inv = rsqrtf(s2 * (1.0f / C_) + 1e-6f);
  float* po = out + (size_t)row * C_;
#pragma unroll
  for (int i = 0; i < 16; i++) {
    int c = lane + 32 * i;
    po[c] = (v[i] - mean) * inv * w[c] + bb[c];
  }
}

// ---------------- launch ----------------
extern "C" void kernel_launch(void* const* d_in, const int* in_sizes, int n_in,
                              void* d_out, int out_size) {
  (void)in_sizes; (void)n_in; (void)out_size;
  const float* spatial = (const float*)d_in[0];
  const float* freq    = (const float*)d_in[1];
  const float* Wq[2] = {(const float*)d_in[2],  (const float*)d_in[7]};
  const float* Wk[2] = {(const float*)d_in[3],  (const float*)d_in[8]};
  const float* Wv[2] = {(const float*)d_in[4],  (const float*)d_in[9]};
  const float* Wo[2] = {(const float*)d_in[5],  (const float*)d_in[10]};
  const float* bo[2] = {(const float*)d_in[6],  (const float*)d_in[11]};
  const float* n1w[2] = {(const float*)d_in[12], (const float*)d_in[16]};
  const float* n1b[2] = {(const float*)d_in[13], (const float*)d_in[17]};
  const float* n2w[2] = {(const float*)d_in[14], (const float*)d_in[18]};
  const float* n2b[2] = {(const float*)d_in[15], (const float*)d_in[19]};
  const float* W1[2] = {(const float*)d_in[20], (const float*)d_in[24]};
  const float* b1[2] = {(const float*)d_in[21], (const float*)d_in[25]};
  const float* W2[2] = {(const float*)d_in[22], (const float*)d_in[26]};
  const float* b2[2] = {(const float*)d_in[23], (const float*)d_in[27]};
  float* out = (float*)d_out;

  float *Xs, *Xf, *Qp, *Kp, *Vp, *Ap, *Ep, *Sp, *Hp, *Fp, *Op;
  __nv_bfloat16 *Ahi, *Alo, *Whi, *Wlo;
  cudaGetSymbolAddress((void**)&Xs, g_Xs);
  cudaGetSymbolAddress((void**)&Xf, g_Xf);
  cudaGetSymbolAddress((void**)&Qp, g_Qb);
  cudaGetSymbolAddress((void**)&Kp, g_Kb);
  cudaGetSymbolAddress((void**)&Vp, g_Vb);
  cudaGetSymbolAddress((void**)&Ap, g_Ab);
  cudaGetSymbolAddress((void**)&Ep, g_Eb);
  cudaGetSymbolAddress((void**)&Sp, g_Sb);
  cudaGetSymbolAddress((void**)&Hp, g_Hb);
  cudaGetSymbolAddress((void**)&Fp, g_Fb);
  cudaGetSymbolAddress((void**)&Op, g_Ob);
  cudaGetSymbolAddress((void**)&Ahi, g_Ahi);
  cudaGetSymbolAddress((void**)&Alo, g_Alo);
  cudaGetSymbolAddress((void**)&Whi, g_Whi);
  cudaGetSymbolAddress((void**)&Wlo, g_Wlo);

  cudaFuncSetAttribute(attn_kernel, cudaFuncAttributeMaxDynamicSharedMemorySize, ATT_SMEM);
  cudaFuncSetAttribute(gemm_mma<0>, cudaFuncAttributeMaxDynamicSharedMemorySize, GT_SMEM);
  cudaFuncSetAttribute(gemm_mma<1>, cudaFuncAttributeMaxDynamicSharedMemorySize, GT_SMEM);

  dim3 tp_threads(32, 8);
  btranspose<<<dim3(HW_ / 32, C_ / 32, B_), tp_threads>>>(spatial, Xs, C_, HW_);
  btranspose<<<dim3(HW_ / 32, C_ / 32, B_), tp_threads>>>(freq, Xf, C_, HW_);

  const int NEL_MC = M_ * C_;
  const int NEL_CC = C_ * C_;
  const int NEL_HC = HID_ * C_;
  const int NEL_MH = M_ * HID_;

  for (int br = 0; br < 2; br++) {
    const float* Xq  = br ? Xf : Xs;
    const float* Xkv = br ? Xs : Xf;

    cvt_split<<<NEL_MC / 1024, 256>>>(Xq, Ahi, Alo);
    cvt_split<<<NEL_CC / 1024, 256>>>(Wq[br], Whi, Wlo);
    gemm_mma<0><<<dim3(C_ / 128, M_ / 128), 256, GT_SMEM>>>(Ahi, Alo, Whi, Wlo, nullptr, Qp, C_, C_);
    cvt_split<<<NEL_MC / 1024, 256>>>(Xkv, Ahi, Alo);
    cvt_split<<<NEL_CC / 1024, 256>>>(Wk[br], Whi, Wlo);
    gemm_mma<0><<<dim3(C_ / 128, M_ / 128), 256, GT_SMEM>>>(Ahi, Alo, Whi, Wlo, nullptr, Kp, C_, C_);
    cvt_split<<<NEL_CC / 1024, 256>>>(Wv[br], Whi, Wlo);
    gemm_mma<0><<<dim3(C_ / 128, M_ / 128), 256, GT_SMEM>>>(Ahi, Alo, Whi, Wlo, nullptr, Vp, C_, C_);

    attn_kernel<<<dim3(16, 8, 8), 256, ATT_SMEM>>>(Qp, Kp, Vp, Ap);

    cvt_split<<<NEL_MC / 1024, 256>>>(Ap, Ahi, Alo);
    cvt_split<<<NEL_CC / 1024, 256>>>(Wo[br], Whi, Wlo);
    gemm_mma<0><<<dim3(C_ / 128, M_ / 128), 256, GT_SMEM>>>(Ahi, Alo, Whi, Wlo, bo[br], Ep, C_, C_);

    ln_res<<<M_ / 8, 256>>>(Xq, Ep, n1w[br], n1b[br], Sp);

    cvt_split<<<NEL_MC / 1024, 256>>>(Sp, Ahi, Alo);
    cvt_split<<<NEL_HC / 1024, 256>>>(W1[br], Whi, Wlo);
    gemm_mma<1><<<dim3(HID_ / 128, M_ / 128), 256, GT_SMEM>>>(Ahi, Alo, Whi, Wlo, b1[br], Hp, HID_, C_);
    cvt_split<<<NEL_MH / 1024, 256>>>(Hp, Ahi, Alo);
    cvt_split<<<NEL_HC / 1024, 256>>>(W2[br], Whi, Wlo);
    gemm_mma<0><<<dim3(C_ / 128, M_ / 128), 256, GT_SMEM>>>(Ahi, Alo, Whi, Wlo, b2[br], Fp, C_, HID_);

    ln_res<<<M_ / 8, 256>>>(Sp, Fp, n2w[br], n2b[br], Op);

    btranspose<<<dim3(C_ / 32, HW_ / 32, B_), tp_threads>>>(Op, out + (size_t)br * M_ * C_, HW_, C_);
  }
}

// round 5
// speedup vs baseline: 2.4109x; 1.4283x over previous
#include <cuda_runtime.h>
#include <cuda_bf16.h>
#include <math.h>
#include <cstdint>

#define B_   8
#define C_   512
#define HW_  1024
#define M_   (B_*HW_)     // 8192 tokens
#define HID_ 2048

// ---------------- scratch (device globals; no allocation) ----------------
__device__ float g_Xs[M_*C_];
__device__ float g_Xf[M_*C_];
__device__ float g_Eb[M_*C_];
__device__ float g_Sb[M_*C_];
__device__ float g_Fb[M_*C_];
__device__ float g_Ob[M_*C_];
__device__ __nv_bfloat16 g_Xshi[M_*C_], g_Xslo[M_*C_];
__device__ __nv_bfloat16 g_Xfhi[M_*C_], g_Xflo[M_*C_];
__device__ __nv_bfloat16 g_QShi[M_*C_], g_QSlo[M_*C_];     // Q, later S split
__device__ __nv_bfloat16 g_KVhi[M_*2*C_], g_KVlo[M_*2*C_]; // K | V concat
__device__ __nv_bfloat16 g_AOhi[M_*C_], g_AOlo[M_*C_];     // attention out
__device__ __nv_bfloat16 g_Hhi[M_*HID_], g_Hlo[M_*HID_];   // FFN hidden
__device__ __nv_bfloat16 g_Whi[HID_*C_], g_Wlo[HID_*C_];   // weight split

// ==================== portable tensor-core helpers ====================
__device__ __forceinline__ uint32_t smem_u32(const void* p) {
  uint32_t a;
  asm("{ .reg .u64 t; cvta.to.shared.u64 t, %1; cvt.u32.u64 %0, t; }" : "=r"(a) : "l"(p));
  return a;
}
__device__ __forceinline__ void ldm_x4(uint32_t* r, uint32_t addr) {
  asm volatile("ldmatrix.sync.aligned.m8n8.x4.shared.b16 {%0,%1,%2,%3}, [%4];"
               : "=r"(r[0]), "=r"(r[1]), "=r"(r[2]), "=r"(r[3]) : "r"(addr));
}
__device__ __forceinline__ void ldm_x4_t(uint32_t* r, uint32_t addr) {
  asm volatile("ldmatrix.sync.aligned.m8n8.x4.trans.shared.b16 {%0,%1,%2,%3}, [%4];"
               : "=r"(r[0]), "=r"(r[1]), "=r"(r[2]), "=r"(r[3]) : "r"(addr));
}
__device__ __forceinline__ void mma16816(float* d, const uint32_t* a, const uint32_t* b) {
  asm volatile("mma.sync.aligned.m16n8k16.row.col.f32.bf16.bf16.f32 "
               "{%0,%1,%2,%3}, {%4,%5,%6,%7}, {%8,%9}, {%0,%1,%2,%3};"
               : "+f"(d[0]), "+f"(d[1]), "+f"(d[2]), "+f"(d[3])
               : "r"(a[0]), "r"(a[1]), "r"(a[2]), "r"(a[3]), "r"(b[0]), "r"(b[1]));
}
__device__ __forceinline__ void cp16(uint32_t saddr, const void* g) {
  asm volatile("cp.async.cg.shared.global [%0], [%1], 16;" :: "r"(saddr), "l"(g));
}
__device__ __forceinline__ void cp_commit() { asm volatile("cp.async.commit_group;" ::: "memory"); }
template <int N>
__device__ __forceinline__ void cp_wait() { asm volatile("cp.async.wait_group %0;" :: "n"(N) : "memory"); }

__device__ __forceinline__ uint32_t pk_bf2(__nv_bfloat16 a, __nv_bfloat16 b) {
  __nv_bfloat162 t; t.x = a; t.y = b;
  return *(uint32_t*)&t;
}
// split (a,b) fp32 pair into hi/lo bf16x2 words
__device__ __forceinline__ void split_pair(float a, float b, uint32_t& hi, uint32_t& lo) {
  __nv_bfloat16 ha = __float2bfloat16(a), hb = __float2bfloat16(b);
  __nv_bfloat16 la = __float2bfloat16(a - __bfloat162float(ha));
  __nv_bfloat16 lb = __float2bfloat16(b - __bfloat162float(hb));
  hi = pk_bf2(ha, hb); lo = pk_bf2(la, lb);
}

__device__ __forceinline__ float gelu_exact(float v) {
  return 0.5f * v * (1.0f + erff(v * 0.70710678118654752f));
}

// ==================== mma.sync GEMM: C[M,N] = A@W^T (+bias,+GELU) ====================
#define BKC 32
#define TSTRIDE 40
#define TILE_B (128*TSTRIDE*2)
#define BUF_B  (4*TILE_B)
#define GT_SMEM (2*BUF_B)

template <int DO_GELU, int SPLIT>
__global__ void __launch_bounds__(256)
gemm_mma(const __nv_bfloat16* __restrict__ Ahi, const __nv_bfloat16* __restrict__ Alo,
         const __nv_bfloat16* __restrict__ Whi, const __nv_bfloat16* __restrict__ Wlo,
         const float* __restrict__ bias, float* __restrict__ Cout,
         __nv_bfloat16* __restrict__ Chi, __nv_bfloat16* __restrict__ Clo,
         int N, int K) {
  extern __shared__ char smem[];
  uint32_t sbase = smem_u32(smem);
  int tid = threadIdx.x, lane = tid & 31, warp = tid >> 5;
  int warp_m = warp & 3, warp_n = warp >> 2;
  int bn = blockIdx.x, bm = blockIdx.y;

  const __nv_bfloat16* src[4];
  src[0] = Ahi + (size_t)bm * 128 * K;
  src[1] = Alo + (size_t)bm * 128 * K;
  src[2] = Whi + (size_t)bn * 128 * K;
  src[3] = Wlo + (size_t)bn * 128 * K;

  auto load_chunk = [&](int buf, int kt) {
    uint32_t bb = sbase + buf * BUF_B;
#pragma unroll
    for (int t = 0; t < 4; t++) {
      const __nv_bfloat16* s = src[t];
      uint32_t tb = bb + t * TILE_B;
#pragma unroll
      for (int i = 0; i < 2; i++) {
        int idx = i * 256 + tid;
        int row = idx >> 2, seg = idx & 3;
        cp16(tb + row * (TSTRIDE * 2) + seg * 16, s + (size_t)row * K + kt + seg * 8);
      }
    }
  };

  float acc[2][8][4];
#pragma unroll
  for (int t = 0; t < 2; t++)
#pragma unroll
    for (int n = 0; n < 8; n++)
#pragma unroll
      for (int j = 0; j < 4; j++) acc[t][n][j] = 0.f;

  int nk = K / BKC;
  load_chunk(0, 0);
  cp_commit();

  for (int i = 0; i < nk; i++) {
    if (i + 1 < nk) {
      load_chunk((i + 1) & 1, (i + 1) * BKC);
      cp_commit();
      cp_wait<1>();
    } else {
      cp_wait<0>();
    }
    __syncthreads();

    uint32_t bb = sbase + (i & 1) * BUF_B;
    uint32_t abase_hi = bb, abase_lo = bb + TILE_B;
    uint32_t wbase_hi = bb + 2 * TILE_B, wbase_lo = bb + 3 * TILE_B;

#pragma unroll
    for (int ks = 0; ks < 2; ks++) {
      uint32_t a_hi[2][4], a_lo[2][4];
#pragma unroll
      for (int t = 0; t < 2; t++) {
        int row = warp_m * 32 + t * 16 + (lane & 15);
        uint32_t off = row * (TSTRIDE * 2) + ks * 32 + (lane >> 4) * 16;
        ldm_x4(a_hi[t], abase_hi + off);
        ldm_x4(a_lo[t], abase_lo + off);
      }
      uint32_t b_hi[8][2], b_lo[8][2];
#pragma unroll
      for (int p = 0; p < 4; p++) {
        int g = lane >> 3;
        int row = warp_n * 64 + p * 16 + ((g >> 1) << 3) + (lane & 7);
        uint32_t off = row * (TSTRIDE * 2) + (g & 1) * 16 + ks * 32;
        uint32_t r4[4];
        ldm_x4(r4, wbase_hi + off);
        b_hi[p * 2][0] = r4[0]; b_hi[p * 2][1] = r4[1];
        b_hi[p * 2 + 1][0] = r4[2]; b_hi[p * 2 + 1][1] = r4[3];
        ldm_x4(r4, wbase_lo + off);
        b_lo[p * 2][0] = r4[0]; b_lo[p * 2][1] = r4[1];
        b_lo[p * 2 + 1][0] = r4[2]; b_lo[p * 2 + 1][1] = r4[3];
      }
#pragma unroll
      for (int t = 0; t < 2; t++)
#pragma unroll
        for (int n = 0; n < 8; n++) {
          mma16816(acc[t][n], a_hi[t], b_hi[n]);
          mma16816(acc[t][n], a_hi[t], b_lo[n]);
          mma16816(acc[t][n], a_lo[t], b_hi[n]);
        }
    }
    __syncthreads();
  }

  int q = lane >> 2, rr = lane & 3;
#pragma unroll
  for (int t = 0; t < 2; t++) {
    int row0 = bm * 128 + warp_m * 32 + t * 16 + q;
#pragma unroll
    for (int n = 0; n < 8; n++) {
      int col = bn * 128 + warp_n * 64 + n * 8 + rr * 2;
      float bx = bias ? bias[col] : 0.f;
      float by = bias ? bias[col + 1] : 0.f;
      float o0x = acc[t][n][0] + bx, o0y = acc[t][n][1] + by;
      float o1x = acc[t][n][2] + bx, o1y = acc[t][n][3] + by;
      if (DO_GELU) {
        o0x = gelu_exact(o0x); o0y = gelu_exact(o0y);
        o1x = gelu_exact(o1x); o1y = gelu_exact(o1y);
      }
      if (SPLIT) {
        uint32_t h0, l0, h1, l1;
        split_pair(o0x, o0y, h0, l0);
        split_pair(o1x, o1y, h1, l1);
        *(uint32_t*)(Chi + (size_t)row0 * N + col) = h0;
        *(uint32_t*)(Clo + (size_t)row0 * N + col) = l0;
        *(uint32_t*)(Chi + (size_t)(row0 + 8) * N + col) = h1;
        *(uint32_t*)(Clo + (size_t)(row0 + 8) * N + col) = l1;
      } else {
        *(float2*)(Cout + (size_t)row0 * N + col) = make_float2(o0x, o0y);
        *(float2*)(Cout + (size_t)(row0 + 8) * N + col) = make_float2(o1x, o1y);
      }
    }
  }
}

// ==================== tensor-core flash attention ====================
// grid (qt 8, h 8, b 8), 256 thr = 8 warps x m16. hi/lo split QK^T and PV.
#define ASTRIDE 144                    // 72 bf16 per smem row (conflict-free)
#define KVT (64*ASTRIDE)               // 9216 B one 64x64 tile
#define ABUF (4*KVT)                   // Khi,Klo,Vhi,Vlo = 36864
#define ATT_SMEM (2*ABUF)              // 73728

__global__ void __launch_bounds__(256) attn_mma(
    const __nv_bfloat16* __restrict__ Qhi, const __nv_bfloat16* __restrict__ Qlo,
    const __nv_bfloat16* __restrict__ KVhi, const __nv_bfloat16* __restrict__ KVlo,
    __nv_bfloat16* __restrict__ Ohi, __nv_bfloat16* __restrict__ Olo) {
  extern __shared__ char smraw[];
  uint32_t sb = smem_u32(smraw);
  int qt = blockIdx.x, h = blockIdx.y, b = blockIdx.z;
  int tid = threadIdx.x, warp = tid >> 5, lane = tid & 31;
  int gid = lane >> 2, tig = lane & 3;

  auto kvload = [&](int buf, int kt) {
    uint32_t bb = sb + buf * ABUF;
    size_t rb = (size_t)(b * HW_ + kt * 64);
#pragma unroll
    for (int i = 0; i < 2; i++) {
      int idx = i * 256 + tid;
      int row = idx >> 3, seg = idx & 7;
      size_t g = (rb + row) * (2 * C_) + h * 64 + seg * 8;
      uint32_t so = row * ASTRIDE + seg * 16;
      cp16(bb + so, KVhi + g);
      cp16(bb + KVT + so, KVlo + g);
      cp16(bb + 2 * KVT + so, KVhi + g + C_);
      cp16(bb + 3 * KVT + so, KVlo + g + C_);
    }
  };

  // stage Q into buf1 (hi @0, lo @+18432), prefetch kv0 into buf0
  {
    const __nv_bfloat16* qh = Qhi + ((size_t)(b * HW_ + qt * 128)) * C_ + h * 64;
    const __nv_bfloat16* ql = Qlo + ((size_t)(b * HW_ + qt * 128)) * C_ + h * 64;
#pragma unroll
    for (int i = 0; i < 4; i++) {
      int idx = i * 256 + tid;
      int row = idx >> 3, seg = idx & 7;
      cp16(sb + ABUF + row * ASTRIDE + seg * 16, qh + (size_t)row * C_ + seg * 8);
      cp16(sb + ABUF + 18432 + row * ASTRIDE + seg * 16, ql + (size_t)row * C_ + seg * 8);
    }
  }
  kvload(0, 0);
  cp_commit();
  cp_wait<0>();
  __syncthreads();

  // extract Q fragments (4 k16 tiles, hi+lo)
  uint32_t qfh[4][4], qfl[4][4];
  {
    uint32_t rowoff = (warp * 16 + (lane & 15)) * ASTRIDE + (lane >> 4) * 16;
#pragma unroll
    for (int t = 0; t < 4; t++) {
      ldm_x4(qfh[t], sb + ABUF + rowoff + t * 32);
      ldm_x4(qfl[t], sb + ABUF + 18432 + rowoff + t * 32);
    }
  }
  __syncthreads();  // buf1 free for kv1

  float m0 = -1e30f, m1 = -1e30f, l0 = 0.f, l1 = 0.f;
  float oacc[8][4];
#pragma unroll
  for (int d = 0; d < 8; d++)
#pragma unroll
    for (int j = 0; j < 4; j++) oacc[d][j] = 0.f;

  int g8 = lane >> 3;
  uint32_t boff_k = (((g8 >> 1) << 3) + (lane & 7)) * ASTRIDE + (g8 & 1) * 16;
  uint32_t boff_v = (8 * (g8 & 1) + (lane & 7)) * ASTRIDE + 16 * (g8 >> 1);

  for (int kt = 0; kt < 16; kt++) {
    if (kt + 1 < 16) {
      kvload((kt + 1) & 1, kt + 1);
      cp_commit();
      cp_wait<1>();
    } else {
      cp_wait<0>();
    }
    __syncthreads();

    uint32_t bb = sb + (kt & 1) * ABUF;
    float sacc[8][4];
#pragma unroll
    for (int j = 0; j < 8; j++)
#pragma unroll
      for (int r = 0; r < 4; r++) sacc[j][r] = 0.f;

    // S = Q K^T
#pragma unroll
    for (int t = 0; t < 4; t++) {
#pragma unroll
      for (int p = 0; p < 4; p++) {
        uint32_t off = p * 16 * ASTRIDE + boff_k + t * 32;
        uint32_t kh[4], kl[4];
        ldm_x4(kh, bb + off);
        ldm_x4(kl, bb + KVT + off);
        mma16816(sacc[2 * p], qfh[t], kh);
        mma16816(sacc[2 * p], qfh[t], kl);
        mma16816(sacc[2 * p], qfl[t], kh);
        mma16816(sacc[2 * p + 1], qfh[t], kh + 2);
        mma16816(sacc[2 * p + 1], qfh[t], kl + 2);
        mma16816(sacc[2 * p + 1], qfl[t], kh + 2);
      }
    }

    // online softmax (rows gid, gid+8; scale 1/8)
#pragma unroll
    for (int j = 0; j < 8; j++)
#pragma unroll
      for (int r = 0; r < 4; r++) sacc[j][r] *= 0.125f;

    float mx0 = -1e30f, mx1 = -1e30f;
#pragma unroll
    for (int j = 0; j < 8; j++) {
      mx0 = fmaxf(mx0, fmaxf(sacc[j][0], sacc[j][1]));
      mx1 = fmaxf(mx1, fmaxf(sacc[j][2], sacc[j][3]));
    }
    mx0 = fmaxf(mx0, __shfl_xor_sync(0xffffffffu, mx0, 1));
    mx0 = fmaxf(mx0, __shfl_xor_sync(0xffffffffu, mx0, 2));
    mx1 = fmaxf(mx1, __shfl_xor_sync(0xffffffffu, mx1, 1));
    mx1 = fmaxf(mx1, __shfl_xor_sync(0xffffffffu, mx1, 2));
    float mn0 = fmaxf(m0, mx0), mn1 = fmaxf(m1, mx1);
    float corr0 = __expf(m0 - mn0), corr1 = __expf(m1 - mn1);
    m0 = mn0; m1 = mn1;
    float ps0 = 0.f, ps1 = 0.f;
#pragma unroll
    for (int j = 0; j < 8; j++) {
      sacc[j][0] = __expf(sacc[j][0] - mn0);
      sacc[j][1] = __expf(sacc[j][1] - mn0);
      sacc[j][2] = __expf(sacc[j][2] - mn1);
      sacc[j][3] = __expf(sacc[j][3] - mn1);
      ps0 += sacc[j][0] + sacc[j][1];
      ps1 += sacc[j][2] + sacc[j][3];
    }
    l0 = l0 * corr0 + ps0;
    l1 = l1 * corr1 + ps1;
#pragma unroll
    for (int d = 0; d < 8; d++) {
      oacc[d][0] *= corr0; oacc[d][1] *= corr0;
      oacc[d][2] *= corr1; oacc[d][3] *= corr1;
    }

    // O += P V  (P packed from sacc fragments)
#pragma unroll
    for (int t = 0; t < 4; t++) {
      uint32_t ahi[4], alo[4];
      split_pair(sacc[2 * t][0], sacc[2 * t][1], ahi[0], alo[0]);
      split_pair(sacc[2 * t][2], sacc[2 * t][3], ahi[1], alo[1]);
      split_pair(sacc[2 * t + 1][0], sacc[2 * t + 1][1], ahi[2], alo[2]);
      split_pair(sacc[2 * t + 1][2], sacc[2 * t + 1][3], ahi[3], alo[3]);
#pragma unroll
      for (int pd = 0; pd < 4; pd++) {
        uint32_t off = t * 16 * ASTRIDE + boff_v + pd * 32;
        uint32_t vh[4], vl[4];
        ldm_x4_t(vh, bb + 2 * KVT + off);
        ldm_x4_t(vl, bb + 3 * KVT + off);
        mma16816(oacc[2 * pd], ahi, vh);
        mma16816(oacc[2 * pd], ahi, vl);
        mma16816(oacc[2 * pd], alo, vh);
        mma16816(oacc[2 * pd + 1], ahi, vh + 2);
        mma16816(oacc[2 * pd + 1], ahi, vl + 2);
        mma16816(oacc[2 * pd + 1], alo, vh + 2);
      }
    }
    __syncthreads();
  }

  l0 += __shfl_xor_sync(0xffffffffu, l0, 1);
  l0 += __shfl_xor_sync(0xffffffffu, l0, 2);
  l1 += __shfl_xor_sync(0xffffffffu, l1, 1);
  l1 += __shfl_xor_sync(0xffffffffu, l1, 2);
  float inv0 = 1.f / l0, inv1 = 1.f / l1;

  size_t q0 = (size_t)(b * HW_ + qt * 128 + warp * 16 + gid);
  size_t q1 = q0 + 8;
#pragma unroll
  for (int d = 0; d < 8; d++) {
    int col = h * 64 + d * 8 + 2 * tig;
    uint32_t h0, lo0, h1, lo1;
    split_pair(oacc[d][0] * inv0, oacc[d][1] * inv0, h0, lo0);
    split_pair(oacc[d][2] * inv1, oacc[d][3] * inv1, h1, lo1);
    *(uint32_t*)(Ohi + q0 * C_ + col) = h0;
    *(uint32_t*)(Olo + q0 * C_ + col) = lo0;
    *(uint32_t*)(Ohi + q1 * C_ + col) = h1;
    *(uint32_t*)(Olo + q1 * C_ + col) = lo1;
  }
}

// ---------------- fp32 -> bf16 hi/lo split ----------------
__global__ void __launch_bounds__(256) cvt_split(const float* __restrict__ x,
                                                 __nv_bfloat16* __restrict__ hi,
                                                 __nv_bfloat16* __restrict__ lo) {
  int i = (blockIdx.x * 256 + threadIdx.x) * 4;
  float4 v = *(const float4*)(x + i);
  uint32_t h0, l0, h1, l1;
  split_pair(v.x, v.y, h0, l0);
  split_pair(v.z, v.w, h1, l1);
  *(uint32_t*)(hi + i) = h0; *(uint32_t*)(hi + i + 2) = h1;
  *(uint32_t*)(lo + i) = l0; *(uint32_t*)(lo + i + 2) = l1;
}

// ---------------- batched transpose ----------------
__global__ void __launch_bounds__(256) btranspose(const float* __restrict__ in,
                                                  float* __restrict__ out,
                                                  int R, int Ccols) {
  __shared__ float t[32][33];
  int b = blockIdx.z;
  const float* pin = in + (size_t)b * R * Ccols;
  float* pout = out + (size_t)b * R * Ccols;
  int c0 = blockIdx.x * 32, r0 = blockIdx.y * 32;
  int x = threadIdx.x, y = threadIdx.y;
#pragma unroll
  for (int j = 0; j < 32; j += 8)
    t[y + j][x] = pin[(size_t)(r0 + y + j) * Ccols + c0 + x];
  __syncthreads();
#pragma unroll
  for (int j = 0; j < 32; j += 8)
    pout[(size_t)(c0 + y + j) * R + r0 + x] = t[x][y + j];
}

// ---------------- LayerNorm(X + Y) over C, optional split out ----------------
template <int SPLIT>
__global__ void __launch_bounds__(256) ln_res(const float* __restrict__ X,
                                              const float* __restrict__ Y,
                                              const float* __restrict__ w,
                                              const float* __restrict__ bb,
                                              float* __restrict__ out,
                                              __nv_bfloat16* __restrict__ ohi,
                                              __nv_bfloat16* __restrict__ olo) {
  int row = blockIdx.x * 8 + (threadIdx.x >> 5);
  int lane = threadIdx.x & 31;
  const float* px = X + (size_t)row * C_;
  const float* py = Y + (size_t)row * C_;
  float2 v[8];
  float s = 0.f;
#pragma unroll
  for (int i = 0; i < 8; i++) {
    float2 a = *(const float2*)&px[2 * lane + 64 * i];
    float2 c = *(const float2*)&py[2 * lane + 64 * i];
    v[i] = make_float2(a.x + c.x, a.y + c.y);
    s += v[i].x + v[i].y;
  }
#pragma unroll
  for (int off = 16; off > 0; off >>= 1) s += __shfl_xor_sync(0xffffffffu, s, off);
  float mean = s * (1.0f / C_);
  float s2 = 0.f;
#pragma unroll
  for (int i = 0; i < 8; i++) {
    float dx = v[i].x - mean, dy = v[i].y - mean;
    s2 += dx * dx + dy * dy;
  }
#pragma unroll
  for (int off = 16; off > 0; off >>= 1) s2 += __shfl_xor_sync(0xffffffffu, s2, off);
  float inv = rsqrtf(s2 * (1.0f / C_) + 1e-6f);
  float* po = out + (size_t)row * C_;
#pragma unroll
  for (int i = 0; i < 8; i++) {
    int c = 2 * lane + 64 * i;
    float ox = (v[i].x - mean) * inv * w[c] + bb[c];
    float oy = (v[i].y - mean) * inv * w[c + 1] + bb[c + 1];
    *(float2*)&po[c] = make_float2(ox, oy);
    if (SPLIT) {
      uint32_t hh, ll;
      split_pair(ox, oy, hh, ll);
      *(uint32_t*)(ohi + (size_t)row * C_ + c) = hh;
      *(uint32_t*)(olo + (size_t)row * C_ + c) = ll;
    }
  }
}

// ---------------- launch ----------------
extern "C" void kernel_launch(void* const* d_in, const int* in_sizes, int n_in,
                              void* d_out, int out_size) {
  (void)in_sizes; (void)n_in; (void)out_size;
  const float* spatial = (const float*)d_in[0];
  const float* freq    = (const float*)d_in[1];
  const float* Wq[2] = {(const float*)d_in[2],  (const float*)d_in[7]};
  const float* Wk[2] = {(const float*)d_in[3],  (const float*)d_in[8]};
  const float* Wv[2] = {(const float*)d_in[4],  (const float*)d_in[9]};
  const float* Wo[2] = {(const float*)d_in[5],  (const float*)d_in[10]};
  const float* bo[2] = {(const float*)d_in[6],  (const float*)d_in[11]};
  const float* n1w[2] = {(const float*)d_in[12], (const float*)d_in[16]};
  const float* n1b[2] = {(const float*)d_in[13], (const float*)d_in[17]};
  const float* n2w[2] = {(const float*)d_in[14], (const float*)d_in[18]};
  const float* n2b[2] = {(const float*)d_in[15], (const float*)d_in[19]};
  const float* W1[2] = {(const float*)d_in[20], (const float*)d_in[24]};
  const float* b1[2] = {(const float*)d_in[21], (const float*)d_in[25]};
  const float* W2[2] = {(const float*)d_in[22], (const float*)d_in[26]};
  const float* b2[2] = {(const float*)d_in[23], (const float*)d_in[27]};
  float* out = (float*)d_out;

  float *Xs, *Xf, *Ep, *Sp, *Fp, *Op;
  __nv_bfloat16 *Xshi, *Xslo, *Xfhi, *Xflo, *QShi, *QSlo, *KVhi, *KVlo;
  __nv_bfloat16 *AOhi, *AOlo, *Hhi, *Hlo, *Whi, *Wlo;
  cudaGetSymbolAddress((void**)&Xs, g_Xs);
  cudaGetSymbolAddress((void**)&Xf, g_Xf);
  cudaGetSymbolAddress((void**)&Ep, g_Eb);
  cudaGetSymbolAddress((void**)&Sp, g_Sb);
  cudaGetSymbolAddress((void**)&Fp, g_Fb);
  cudaGetSymbolAddress((void**)&Op, g_Ob);
  cudaGetSymbolAddress((void**)&Xshi, g_Xshi);
  cudaGetSymbolAddress((void**)&Xslo, g_Xslo);
  cudaGetSymbolAddress((void**)&Xfhi, g_Xfhi);
  cudaGetSymbolAddress((void**)&Xflo, g_Xflo);
  cudaGetSymbolAddress((void**)&QShi, g_QShi);
  cudaGetSymbolAddress((void**)&QSlo, g_QSlo);
  cudaGetSymbolAddress((void**)&KVhi, g_KVhi);
  cudaGetSymbolAddress((void**)&KVlo, g_KVlo);
  cudaGetSymbolAddress((void**)&AOhi, g_AOhi);
  cudaGetSymbolAddress((void**)&AOlo, g_AOlo);
  cudaGetSymbolAddress((void**)&Hhi, g_Hhi);
  cudaGetSymbolAddress((void**)&Hlo, g_Hlo);
  cudaGetSymbolAddress((void**)&Whi, g_Whi);
  cudaGetSymbolAddress((void**)&Wlo, g_Wlo);

  cudaFuncSetAttribute(attn_mma, cudaFuncAttributeMaxDynamicSharedMemorySize, ATT_SMEM);
  cudaFuncSetAttribute(gemm_mma<0, 0>, cudaFuncAttributeMaxDynamicSharedMemorySize, GT_SMEM);
  cudaFuncSetAttribute(gemm_mma<0, 1>, cudaFuncAttributeMaxDynamicSharedMemorySize, GT_SMEM);
  cudaFuncSetAttribute(gemm_mma<1, 1>, cudaFuncAttributeMaxDynamicSharedMemorySize, GT_SMEM);

  dim3 tp_threads(32, 8);
  btranspose<<<dim3(HW_ / 32, C_ / 32, B_), tp_threads>>>(spatial, Xs, C_, HW_);
  btranspose<<<dim3(HW_ / 32, C_ / 32, B_), tp_threads>>>(freq, Xf, C_, HW_);

  const int NEL_MC = M_ * C_;
  const int NEL_CC = C_ * C_;
  const int NEL_HC = HID_ * C_;

  // split inputs once (shared by both branches)
  cvt_split<<<NEL_MC / 1024, 256>>>(Xs, Xshi, Xslo);
  cvt_split<<<NEL_MC / 1024, 256>>>(Xf, Xfhi, Xflo);

  for (int br = 0; br < 2; br++) {
    const float* Xq = br ? Xf : Xs;
    const __nv_bfloat16* Xqhi  = br ? Xfhi : Xshi;
    const __nv_bfloat16* Xqlo  = br ? Xflo : Xslo;
    const __nv_bfloat16* Xkvhi = br ? Xshi : Xfhi;
    const __nv_bfloat16* Xkvlo = br ? Xslo : Xflo;

    // Q = Xq Wq^T  (split out)
    cvt_split<<<NEL_CC / 1024, 256>>>(Wq[br], Whi, Wlo);
    gemm_mma<0, 1><<<dim3(4, 64), 256, GT_SMEM>>>(Xqhi, Xqlo, Whi, Wlo, nullptr,
                                                  nullptr, QShi, QSlo, C_, C_);
    // KV = Xkv [Wk;Wv]^T  (N=1024, split out)
    cvt_split<<<NEL_CC / 1024, 256>>>(Wk[br], Whi, Wlo);
    cvt_split<<<NEL_CC / 1024, 256>>>(Wv[br], Whi + NEL_CC, Wlo + NEL_CC);
    gemm_mma<0, 1><<<dim3(8, 64), 256, GT_SMEM>>>(Xkvhi, Xkvlo, Whi, Wlo, nullptr,
                                                  nullptr, KVhi, KVlo, 2 * C_, C_);

    attn_mma<<<dim3(8, 8, 8), 256, ATT_SMEM>>>(QShi, QSlo, KVhi, KVlo, AOhi, AOlo);

    // E = AO Wo^T + bo  (fp32 out)
    cvt_split<<<NEL_CC / 1024, 256>>>(Wo[br], Whi, Wlo);
    gemm_mma<0, 0><<<dim3(4, 64), 256, GT_SMEM>>>(AOhi, AOlo, Whi, Wlo, bo[br],
                                                  Ep, nullptr, nullptr, C_, C_);
    // S = LN(Xq + E)  (fp32 + split)
    ln_res<1><<<M_ / 8, 256>>>(Xq, Ep, n1w[br], n1b[br], Sp, QShi, QSlo);

    // H = gelu(S W1^T + b1)  (split out)
    cvt_split<<<NEL_HC / 1024, 256>>>(W1[br], Whi, Wlo);
    gemm_mma<1, 1><<<dim3(16, 64), 256, GT_SMEM>>>(QShi, QSlo, Whi, Wlo, b1[br],
                                                   nullptr, Hhi, Hlo, HID_, C_);
    // F = H W2^T + b2  (fp32 out)
    cvt_split<<<NEL_HC / 1024, 256>>>(W2[br], Whi, Wlo);
    gemm_mma<0, 0><<<dim3(4, 64), 256, GT_SMEM>>>(Hhi, Hlo, Whi, Wlo, b2[br],
                                                  Fp, nullptr, nullptr, C_, HID_);

    ln_res<0><<<M_ / 8, 256>>>(Sp, Fp, n2w[br], n2b[br], Op, nullptr, nullptr);

    btranspose<<<dim3(C_ / 32, HW_ / 32, B_), tp_threads>>>(Op, out + (size_t)br * M_ * C_, HW_, C_);
  }
}